// round 16
// baseline (speedup 1.0000x reference)
#include <cuda_runtime.h>
#include <math_constants.h>

// Problem constants
#define NPOS 65536   // 64 * 32 * 32 positions
#define DIM  64      // embedding dim
#define KCB  512     // codebook size
#define NCHW_ELEMS 4194304  // 64*64*32*32
#define GRID 1024

typedef unsigned long long ull;

// Scratch (allocation-free: __device__ globals)
// g_hist[0..511] = histogram, [512] = ne-ready flag, [513] = completion ctr.
// All zeroed each replay by the memset node in kernel_launch.
__device__ int   g_hist[KCB + 2];
__device__ float g_ne[KCB];          // ||e_k||^2 in fp32
__device__ float g_partial[GRID];

// Packed fp32x2 FMA (Blackwell): per-lane IEEE identical to scalar fmaf.
__device__ __forceinline__ void ffma2(ull& acc, ull a, ull b) {
    asm("fma.rn.f32x2 %0, %1, %2, %0;" : "+l"(acc) : "l"(a), "l"(b));
}
__device__ __forceinline__ ull dup2(float v) {
    ull r;
    asm("mov.b64 %0, {%1, %1};" : "=l"(r) : "f"(v));
    return r;
}
__device__ __forceinline__ void unpack2(ull p, float& lo, float& hi) {
    asm("mov.b64 {%0, %1}, %2;" : "=f"(lo), "=f"(hi) : "l"(p));
}

// ---------------------------------------------------------------------------
// Single fused kernel: in-kernel ne producer/spin + FFMA2 argmin GEMM
// (R9 core verbatim) + fused outputs + loss partial + last-block finalize
// (approx log/exp: tiny register footprint).
// dist = fl32(fl32(nx+ne) - fl32(2*s)), first-index argmin (jax emulation).
// Grid: 1024 blocks x 256 threads. Block = 64 positions x 512 codes.
// ---------------------------------------------------------------------------
__global__ __launch_bounds__(256, 2) void vq_fused_kernel(
    const float* __restrict__ x, const float* __restrict__ emb,
    float* __restrict__ out)
{
    __shared__ float Xs[64 * 64];      // [d][pos], d-major (pos pairs adjacent)
    __shared__ float Es[128 * 65];     // [code][d] pad 65; reused as qs[64][65]
    __shared__ float nes[KCB];         // ||e_k||^2 staged
    __shared__ float xpart[4 * 64];    // nx partials; reused as reduction buf
    __shared__ float xn[64];           // ||x_p||^2 (binade-correct suffices)
    __shared__ int   widx[64];         // winning code per position
    __shared__ int   isLast;

    const int tid = threadIdx.x;
    const int posBase = blockIdx.x * 64;
    const int b  = posBase >> 10;       // 1024 positions per batch image
    const int hw = posBase & 1023;
    const float* xb = x + (size_t)b * 65536 + hw;  // + d*1024 + p

    // ---- ne producer: blocks 0-15 (wave-1 residents), warp 0, 1 code/lane.
    // Bit-identical fmaf chain; unroll 8 keeps live registers low (R14 lesson).
    if (blockIdx.x < 16 && tid < 32) {
        int k = blockIdx.x * 32 + tid;
        const float4* e4 = (const float4*)(emb + k * DIM);
        float s = 0.f;
#pragma unroll 8
        for (int j = 0; j < 16; ++j) {
            float4 v = e4[j];
            s = fmaf(v.x, v.x, s);
            s = fmaf(v.y, v.y, s);
            s = fmaf(v.z, v.z, s);
            s = fmaf(v.w, v.w, s);
        }
        g_ne[k] = s;
        __threadfence();
        atomicAdd(&g_hist[KCB], 1);    // flag: counts ne entries published
    }

    // Load X tile (float4, coalesced): Xs[d*64+p] — overlaps ne compute/spin
#pragma unroll
    for (int it = 0; it < 4; ++it) {
        int j = it * 1024 + tid * 4;
        int d = j >> 6, p = j & 63;
        *(float4*)&Xs[d * 64 + p] = *(const float4*)&xb[d * 1024 + p];
    }

    // ---- spin until all 512 ne published (atomics are L2-coherent)
    if (tid == 0) {
        while (atomicAdd(&g_hist[KCB], 0) < KCB) __nanosleep(64);
    }
    __syncthreads();
    // Stage ne (L1-bypassing loads; producers wrote after kernel start)
    nes[tid]       = __ldcg(&g_ne[tid]);
    nes[tid + 256] = __ldcg(&g_ne[tid + 256]);
    __syncthreads();

    // nx per position — R9-verbatim chains (bits shift fl(nx+ne) boundaries)
    {
        int p = tid & 63, g = tid >> 6;
        float s = 0.f;
#pragma unroll
        for (int j = 0; j < 16; ++j) {
            float v = Xs[(g * 16 + j) * 64 + p];
            s = fmaf(v, v, s);
        }
        xpart[g * 64 + p] = s;
    }
    __syncthreads();
    if (tid < 64) {
        xn[tid] = ((xpart[tid] + xpart[64 + tid]) + xpart[128 + tid]) + xpart[192 + tid];
    }

    const int ry = tid >> 5;
    const int cx = tid & 31;

    float best[8];
    int   bidx[8];
#pragma unroll
    for (int i = 0; i < 8; ++i) { best[i] = CUDART_INF_F; bidx[i] = 0; }

    for (int ch = 0; ch < 4; ++ch) {
        __syncthreads();
        // Load E chunk (128 codes x 64 d), scalar stores (R5 pattern)
#pragma unroll
        for (int it = 0; it < 8; ++it) {
            int j  = it * 1024 + tid * 4;
            int cc = j >> 6, d = j & 63;
            float4 e4 = *(const float4*)&emb[(ch * 128 + cc) * DIM + d];
            float* row = &Es[cc * 65 + d];
            row[0] = e4.x; row[1] = e4.y; row[2] = e4.z; row[3] = e4.w;
        }
        __syncthreads();

        // acc[g][j]: code group g (k = ch*128+cx+32g), position pair j
        ull acc[4][4];
#pragma unroll
        for (int g = 0; g < 4; ++g)
#pragma unroll
            for (int j = 0; j < 4; ++j) acc[g][j] = 0ull;

#pragma unroll 16
        for (int d = 0; d < 64; ++d) {
            // scalar e loads: bank = (cx + d) % 32 -> conflict-free
            ull e0 = dup2(Es[(cx      ) * 65 + d]);
            ull e1 = dup2(Es[(cx + 32 ) * 65 + d]);
            ull e2 = dup2(Es[(cx + 64 ) * 65 + d]);
            ull e3 = dup2(Es[(cx + 96 ) * 65 + d]);
            // broadcast 128-bit shared loads: 4 packed position-pairs
            const ulonglong2 a0 = *(const ulonglong2*)&Xs[d * 64 + ry * 8];
            const ulonglong2 a1 = *(const ulonglong2*)&Xs[d * 64 + ry * 8 + 4];
            ffma2(acc[0][0], a0.x, e0); ffma2(acc[0][1], a0.y, e0);
            ffma2(acc[0][2], a1.x, e0); ffma2(acc[0][3], a1.y, e0);
            ffma2(acc[1][0], a0.x, e1); ffma2(acc[1][1], a0.y, e1);
            ffma2(acc[1][2], a1.x, e1); ffma2(acc[1][3], a1.y, e1);
            ffma2(acc[2][0], a0.x, e2); ffma2(acc[2][1], a0.y, e2);
            ffma2(acc[2][2], a1.x, e2); ffma2(acc[2][3], a1.y, e2);
            ffma2(acc[3][0], a0.x, e3); ffma2(acc[3][1], a0.y, e3);
            ffma2(acc[3][2], a1.x, e3); ffma2(acc[3][3], a1.y, e3);
        }

        // Epilogue: emulate jax rounding, running first-index argmin.
        // g ascending => code index ascending within thread.
#pragma unroll
        for (int g = 0; g < 4; ++g) {
            const int k = ch * 128 + cx + g * 32;
            const float ne = nes[k];
#pragma unroll
            for (int j = 0; j < 4; ++j) {
                float sa, sb;
                unpack2(acc[g][j], sa, sb);
                float nxa = xn[ry * 8 + 2 * j];
                float nxb = xn[ry * 8 + 2 * j + 1];
                float da = __fsub_rn(__fadd_rn(nxa, ne), __fmul_rn(2.0f, sa));
                float db = __fsub_rn(__fadd_rn(nxb, ne), __fmul_rn(2.0f, sb));
                if (da < best[2 * j])     { best[2 * j]     = da; bidx[2 * j]     = k; }
                if (db < best[2 * j + 1]) { best[2 * j + 1] = db; bidx[2 * j + 1] = k; }
            }
        }
    }

    // Warp butterfly argmin per position (tie -> smaller index)
#pragma unroll
    for (int i = 0; i < 8; ++i) {
        float v = best[i];
        int   id = bidx[i];
#pragma unroll
        for (int off = 16; off > 0; off >>= 1) {
            float ov = __shfl_xor_sync(0xffffffffu, v, off);
            int   oi = __shfl_xor_sync(0xffffffffu, id, off);
            if (ov < v || (ov == v && oi < id)) { v = ov; id = oi; }
        }
        if (cx == 0) {
            widx[ry * 8 + i] = id;
            atomicAdd(&g_hist[id], 1);
        }
    }
    __syncthreads();

    // ---------------- fused output (Es reused as qs[64][65]) ----------------
    float* out_nchw = out + 1;
    float* out_flat = out + 2 + NCHW_ELEMS;

    // Pass 1 (pos-major): coalesced codebook gather into qs
#pragma unroll
    for (int it = 0; it < 16; ++it) {
        int j = it * 256 + tid;
        int p = j >> 6, d = j & 63;
        Es[p * 65 + d] = emb[widx[p] * DIM + d];
    }
    __syncthreads();

    // Pass 2 (d-major): x from resident Xs, NCHW q_st write, loss accumulation
    float lsum = 0.f;
#pragma unroll
    for (int it = 0; it < 16; ++it) {
        int j = it * 256 + tid;
        int d = j >> 6, p = j & 63;
        size_t g = (size_t)b * 65536 + (size_t)d * 1024 + hw + p;
        float q  = Es[p * 65 + d];          // stride 65 -> conflict-free
        float xv = Xs[d * 64 + p];
        float df  = __fsub_rn(q, xv);       // fl32(q - x)
        float qst = __fadd_rn(xv, df);      // fl32(x + (q - x))
        out_nchw[g] = qst;
        Es[p * 65 + d] = qst;
        lsum = fmaf(df, df, lsum);
    }
    __syncthreads();

    // Pass 3 (pos-major): flat NHWC q_st write (coalesced)
#pragma unroll
    for (int it = 0; it < 16; ++it) {
        int j = it * 256 + tid;
        int p = j >> 6, d = j & 63;
        out_flat[(size_t)(posBase + p) * DIM + d] = Es[p * 65 + d];
    }

    // Loss partial; reuse xpart as red[256]
    float* red = xpart;
    red[tid] = lsum;
    __syncthreads();
    for (int s = 128; s > 0; s >>= 1) {
        if (tid < s) red[tid] += red[tid + s];
        __syncthreads();
    }
    if (tid == 0) g_partial[blockIdx.x] = red[0];

    // ---------------- last-block finalize (approx log/exp: tiny regs) -------
    __threadfence();
    __syncthreads();
    if (tid == 0) {
        int c = atomicAdd(&g_hist[KCB + 1], 1);
        isLast = (c == GRID - 1);
    }
    __syncthreads();
    if (!isLast) return;

    __threadfence();
    // Loss: 1024 partials -> 256 -> tree (R13 grouping; ~1e-8 rel shift only)
    red[tid] = (__ldcg(&g_partial[tid])       + __ldcg(&g_partial[tid + 256]))
             + (__ldcg(&g_partial[tid + 512]) + __ldcg(&g_partial[tid + 768]));
    __syncthreads();
    for (int s = 128; s > 0; s >>= 1) {
        if (tid < s) red[tid] += red[tid + s];
        __syncthreads();
    }
    if (tid == 0) {
        out[0] = 1.25f * (red[0] / (float)NCHW_ELEMS);
    }
    __syncthreads();

    // Perplexity: __logf/__expf (approx; rel err ~2e-6 << 1e-3 tolerance)
    float p0 = (float)__ldcg(&g_hist[tid])       * (1.0f / 65536.0f);
    float p1 = (float)__ldcg(&g_hist[tid + 256]) * (1.0f / 65536.0f);
    red[tid] = p0 * __logf(p0 + 1e-10f) + p1 * __logf(p1 + 1e-10f);
    __syncthreads();
    for (int s = 128; s > 0; s >>= 1) {
        if (tid < s) red[tid] += red[tid + s];
        __syncthreads();
    }
    if (tid == 0) {
        out[NCHW_ELEMS + 1] = __expf(-red[0]);
    }
}

// ---------------------------------------------------------------------------
extern "C" void kernel_launch(void* const* d_in, const int* in_sizes, int n_in,
                              void* d_out, int out_size) {
    const float* x   = (const float*)d_in[0];   // [64,64,32,32] f32 NCHW
    const float* emb = (const float*)d_in[1];   // [512,64] f32
    float* out = (float*)d_out;

    // Zero histogram + flag + completion counter (graph memset node)
    void* hp = nullptr;
    cudaGetSymbolAddress(&hp, g_hist);
    cudaMemsetAsync(hp, 0, (KCB + 2) * sizeof(int));

    vq_fused_kernel<<<GRID, 256>>>(x, emb, out);
}